// round 1
// baseline (speedup 1.0000x reference)
#include <cuda_runtime.h>
#include <math.h>

typedef unsigned long long ull;

#define NPTS 524288
#define TSZ  (1u << 19)
#define P1   2654435761u
#define P2   805459861u

// ---------------- scratch (device globals; allocation-free rule) ----------------
__device__ float g_F [(size_t)NPTS * 72];    // encoded features, col 71 = 0 pad
__device__ float g_H0[(size_t)NPTS * 256];
__device__ float g_H1[(size_t)NPTS * 256];
__device__ float g_W0[72  * 256];            // [K=72 ][J=256], row 71 stays zero (BSS)
__device__ float g_W1[256 * 256];            // [K=256][J=256]
__device__ float g_W2[256 * 260];            // [K=256][J<=257], ld=260 for alignment

struct LevelParams { int R[16]; int dense[16]; };

// ---------------- weight-norm fold: Wt[k][j] = g[j] * v[j][k] / ||v[j]|| --------
__global__ void prep_weights_kernel(const float* __restrict__ v,
                                    const float* __restrict__ g,
                                    float* __restrict__ Wt, int Kdim, int ldb)
{
    int j = blockIdx.x;
    const float* vr = v + (size_t)j * Kdim;
    __shared__ float red[256];
    float s = 0.f;
    for (int k = threadIdx.x; k < Kdim; k += 256) { float t = vr[k]; s += t * t; }
    red[threadIdx.x] = s;
    __syncthreads();
    for (int st = 128; st > 0; st >>= 1) {
        if (threadIdx.x < st) red[threadIdx.x] += red[threadIdx.x + st];
        __syncthreads();
    }
    float scale = g[j] * rsqrtf(red[0]);
    for (int k = threadIdx.x; k < Kdim; k += 256)
        Wt[(size_t)k * ldb + j] = vr[k] * scale;
}

// ---------------- encode: pos-embed + multires hash grid ------------------------
__global__ void encode_kernel(const float* __restrict__ x,
                              const float* __restrict__ tab,
                              float* __restrict__ F, LevelParams lp)
{
    int i = blockIdx.x * blockDim.x + threadIdx.x;
    if (i >= NPTS) return;
    float px = x[3 * i + 0], py = x[3 * i + 1], pz = x[3 * i + 2];
    float* Frow = F + (size_t)i * 72;

    Frow[0] = px; Frow[1] = py; Frow[2] = pz;
#pragma unroll
    for (int j = 0; j < 6; j++) {
        float f = (float)(1 << j);
        float s0, c0, s1, c1, s2, c2;
        sincosf(f * px, &s0, &c0);
        sincosf(f * py, &s1, &c1);
        sincosf(f * pz, &s2, &c2);
        Frow[3 + 6 * j + 0] = s0; Frow[3 + 6 * j + 1] = s1; Frow[3 + 6 * j + 2] = s2;
        Frow[3 + 6 * j + 3] = c0; Frow[3 + 6 * j + 4] = c1; Frow[3 + 6 * j + 5] = c2;
    }

    float xc = fminf(fmaxf(px, 0.f), 1.f);
    float yc = fminf(fmaxf(py, 0.f), 1.f);
    float zc = fminf(fmaxf(pz, 0.f), 1.f);

    for (int l = 0; l < 16; l++) {
        int   R  = lp.R[l];
        float Rf = (float)R;
        float fx = xc * Rf, fy = yc * Rf, fz = zc * Rf;
        float f0x = floorf(fx), f0y = floorf(fy), f0z = floorf(fz);
        float w1x = fx - f0x, w1y = fy - f0y, w1z = fz - f0z;
        float wx[2] = {1.f - w1x, w1x};
        float wy[2] = {1.f - w1y, w1y};
        float wz[2] = {1.f - w1z, w1z};
        unsigned ux = (unsigned)f0x, uy = (unsigned)f0y, uz = (unsigned)f0z;
        unsigned Ru = (unsigned)R, R1 = Ru + 1u;
        int dns = lp.dense[l];
        const float2* tabL = (const float2*)tab + (size_t)l * TSZ;
        float ax = 0.f, ay = 0.f;
#pragma unroll
        for (int c = 0; c < 8; c++) {
            unsigned ox = c & 1, oy = (c >> 1) & 1, oz = (c >> 2) & 1;
            unsigned ix = min(ux + ox, Ru);
            unsigned iy = min(uy + oy, Ru);
            unsigned iz = min(uz + oz, Ru);
            unsigned flat;
            if (dns) flat = ix + R1 * (iy + R1 * iz);
            else     flat = (ix ^ (iy * P1) ^ (iz * P2)) & (TSZ - 1u);
            float wc = wx[ox] * wy[oy] * wz[oz];
            float2 tv = __ldg(&tabL[flat]);
            ax = fmaf(wc, tv.x, ax);
            ay = fmaf(wc, tv.y, ay);
        }
        Frow[39 + 2 * l]     = ax;
        Frow[39 + 2 * l + 1] = ay;
    }
    Frow[71] = 0.f;
}

// ---------------- fp32 GEMM with packed fma.rn.f32x2 ----------------------------
// C[M,J] = act(A[M,K] @ B^T + bias), B given transposed as Wt[K][ldb].
// BM=BN=128, BK=8, 256 threads, 8x8 microtile as 8 rows x 4 col-pair f32x2 accs.
#define FMA2(c, a, b) asm("fma.rn.f32x2 %0, %1, %2, %0;" : "+l"(c) : "l"(a), "l"(b))

__device__ __forceinline__ float softplus100(float v) {
    float y = 100.f * v;
    if (y > 20.f) return v;
    return log1pf(__expf(y)) * 0.01f;
}

template<int K, bool ACT>
__global__ __launch_bounds__(256, 2)
void gemm_kernel(const float* __restrict__ A, const float* __restrict__ B,
                 const float* __restrict__ bias, float* __restrict__ C,
                 int ldb, int ldc)
{
    constexpr int BK = 8;
    constexpr int AS = 260;                     // As2 row stride (floats): dup A layout
    __shared__ __align__(16) float As2[BK * AS]; // As2[k][2*row+{0,1}] = a (duplicated)
    __shared__ __align__(16) float Bs [BK * 128];

    int tid = threadIdx.x;
    int tx = tid & 15, ty = tid >> 4;
    int mBase = blockIdx.y * 128;
    int nBase = blockIdx.x * 128;

    // global tile load mapping
    int arow = tid >> 1, acol = (tid & 1) * 4;           // A: float4 per thread
    int brow = tid >> 5, bcol = (tid & 31) * 4;          // B: float4 per thread
    const float* Aptr = A + (size_t)(mBase + arow) * K + acol;
    const float* Bptr = B + (size_t)brow * ldb + nBase + bcol;

    ull acc[8][4];
#pragma unroll
    for (int i = 0; i < 8; i++)
#pragma unroll
        for (int p = 0; p < 4; p++) acc[i][p] = 0ull;

    float4 aReg = *(const float4*)Aptr;
    float4 bReg = *(const float4*)Bptr;

    const int nk = K / BK;
    for (int kt = 0; kt < nk; kt++) {
        // stage A duplicated, B straight
        {
            float av[4] = {aReg.x, aReg.y, aReg.z, aReg.w};
#pragma unroll
            for (int q = 0; q < 4; q++) {
                float2 d = make_float2(av[q], av[q]);
                *(float2*)&As2[(acol + q) * AS + 2 * arow] = d;
            }
            *(float4*)&Bs[brow * 128 + bcol] = bReg;
        }
        __syncthreads();

        if (kt + 1 < nk) {
            aReg = *(const float4*)(Aptr + (kt + 1) * 8);
            bReg = *(const float4*)(Bptr + (size_t)(kt + 1) * 8 * ldb);
        }

#pragma unroll
        for (int k = 0; k < BK; k++) {
            ull a[8], b[4];
            ulonglong2 t;
            t = *(const ulonglong2*)&As2[k * AS + ty * 16 +  0]; a[0] = t.x; a[1] = t.y;
            t = *(const ulonglong2*)&As2[k * AS + ty * 16 +  4]; a[2] = t.x; a[3] = t.y;
            t = *(const ulonglong2*)&As2[k * AS + ty * 16 +  8]; a[4] = t.x; a[5] = t.y;
            t = *(const ulonglong2*)&As2[k * AS + ty * 16 + 12]; a[6] = t.x; a[7] = t.y;
            t = *(const ulonglong2*)&Bs [k * 128 + tx * 8 + 0];  b[0] = t.x; b[1] = t.y;
            t = *(const ulonglong2*)&Bs [k * 128 + tx * 8 + 4];  b[2] = t.x; b[3] = t.y;
#pragma unroll
            for (int i = 0; i < 8; i++)
#pragma unroll
                for (int p = 0; p < 4; p++)
                    FMA2(acc[i][p], a[i], b[p]);
        }
        __syncthreads();
    }

    // epilogue: bias + activation
    float bj[8];
#pragma unroll
    for (int j = 0; j < 8; j++) bj[j] = bias[nBase + tx * 8 + j];

#pragma unroll
    for (int i = 0; i < 8; i++) {
        float* crow = C + (size_t)(mBase + ty * 8 + i) * ldc + nBase + tx * 8;
#pragma unroll
        for (int p = 0; p < 4; p++) {
            float2 v = *(float2*)&acc[i][p];
            float o0 = v.x + bj[2 * p];
            float o1 = v.y + bj[2 * p + 1];
            if (ACT) { o0 = softplus100(o0); o1 = softplus100(o1); }
            crow[2 * p]     = o0;
            crow[2 * p + 1] = o1;
        }
    }
}

// ---------------- last output column (row 256 of W2) ----------------------------
__global__ void lastcol_kernel(const float* __restrict__ H1,
                               const float* __restrict__ W2,
                               const float* __restrict__ b2,
                               float* __restrict__ out)
{
    __shared__ float w[256];
    int tid = threadIdx.x;
    w[tid] = W2[(size_t)tid * 260 + 256];
    __syncthreads();
    int lane = tid & 31, warp = tid >> 5;
    size_t i = (size_t)blockIdx.x * 8 + warp;
    const float* h = H1 + i * 256;
    float s = 0.f;
#pragma unroll
    for (int q = 0; q < 8; q++) s = fmaf(h[lane + 32 * q], w[lane + 32 * q], s);
#pragma unroll
    for (int off = 16; off > 0; off >>= 1) s += __shfl_xor_sync(0xffffffffu, s, off);
    if (lane == 0) out[i * 257 + 256] = s + b2[256];
}

// ---------------- launch --------------------------------------------------------
extern "C" void kernel_launch(void* const* d_in, const int* in_sizes, int n_in,
                              void* d_out, int out_size)
{
    const float* x      = (const float*)d_in[0];
    const float* tables = (const float*)d_in[1];
    const float* v0 = (const float*)d_in[2];
    const float* g0 = (const float*)d_in[3];
    const float* b0 = (const float*)d_in[4];
    const float* v1 = (const float*)d_in[5];
    const float* g1 = (const float*)d_in[6];
    const float* b1 = (const float*)d_in[7];
    const float* v2 = (const float*)d_in[8];
    const float* g2 = (const float*)d_in[9];
    const float* b2 = (const float*)d_in[10];
    float* out = (float*)d_out;

    float *F, *H0, *H1, *W0, *W1, *W2;
    cudaGetSymbolAddress((void**)&F,  g_F);
    cudaGetSymbolAddress((void**)&H0, g_H0);
    cudaGetSymbolAddress((void**)&H1, g_H1);
    cudaGetSymbolAddress((void**)&W0, g_W0);
    cudaGetSymbolAddress((void**)&W1, g_W1);
    cudaGetSymbolAddress((void**)&W2, g_W2);

    // level resolutions, matching numpy: R = ceil(16 * (2^(7/15))^l) via libm pow
    LevelParams lp;
    double SCALE = pow(2.0, log2(2048.0 / 16.0) / 15.0);
    for (int l = 0; l < 16; l++) {
        int R = (int)ceil(16.0 * pow(SCALE, (double)l));
        lp.R[l] = R;
        long long c = (long long)R + 1;
        lp.dense[l] = (c * c * c <= (long long)TSZ) ? 1 : 0;
    }

    prep_weights_kernel<<<256, 256>>>(v0, g0, W0, 71, 256);
    prep_weights_kernel<<<256, 256>>>(v1, g1, W1, 256, 256);
    prep_weights_kernel<<<257, 256>>>(v2, g2, W2, 256, 260);

    encode_kernel<<<NPTS / 256, 256>>>(x, tables, F, lp);

    dim3 grid(2, NPTS / 128);
    gemm_kernel< 72, true ><<<grid, 256>>>(F,  W0, b0, H0, 256, 256);
    gemm_kernel<256, true ><<<grid, 256>>>(H0, W1, b1, H1, 256, 256);
    gemm_kernel<256, false><<<grid, 256>>>(H1, W2, b2, out, 260, 257);

    lastcol_kernel<<<NPTS / 8, 256>>>(H1, W2, b2, out);
}

// round 3
// speedup vs baseline: 1.9347x; 1.9347x over previous
#include <cuda_runtime.h>
#include <cuda_bf16.h>
#include <math.h>
#include <stdint.h>

typedef unsigned int uint32;

#define NPTS 524288
#define TSZ  (1u << 19)
#define P1   2654435761u
#define P2   805459861u

// ---------------- scratch (device globals; allocation-free rule) ----------------
// Padding regions (cols 71..127 of F, rows k>=71 of W0) are BSS-zero and never
// written by any kernel, so they stay zero across graph replays.
__device__ __nv_bfloat16 g_Fhi [(size_t)NPTS * 128];
__device__ __nv_bfloat16 g_Flo [(size_t)NPTS * 128];
__device__ __nv_bfloat16 g_H0hi[(size_t)NPTS * 256];
__device__ __nv_bfloat16 g_H0lo[(size_t)NPTS * 256];
__device__ __nv_bfloat16 g_H1hi[(size_t)NPTS * 256];
__device__ __nv_bfloat16 g_H1lo[(size_t)NPTS * 256];
__device__ __nv_bfloat16 g_W0hi[256 * 128];            // [N=256][Kpad=128] K-major
__device__ __nv_bfloat16 g_W0lo[256 * 128];
__device__ __nv_bfloat16 g_W1hi[256 * 256];
__device__ __nv_bfloat16 g_W1lo[256 * 256];
__device__ __nv_bfloat16 g_W2hi[256 * 256];            // rows 0..255 of v2
__device__ __nv_bfloat16 g_W2lo[256 * 256];
__device__ float         g_w2last[256];                // row 256 of v2 (folded)

struct LevelParams { int R[16]; int dense[16]; };

// ---------------- PTX helpers ---------------------------------------------------
__device__ __forceinline__ uint32 smem_u32(const void* p) {
    uint32 a;
    asm("{ .reg .u64 t; cvta.to.shared.u64 t, %1; cvt.u32.u64 %0, t; }" : "=r"(a) : "l"(p));
    return a;
}

#define CP_ASYNC16(dst, src) asm volatile("cp.async.cg.shared.global [%0], [%1], 16;" :: "r"(dst), "l"(src))
#define CP_COMMIT()          asm volatile("cp.async.commit_group;" ::: "memory")
#define CP_WAIT(n)           asm volatile("cp.async.wait_group %0;" :: "n"(n) : "memory")

#define LDSM4(r0, r1, r2, r3, addr) \
    asm volatile("ldmatrix.sync.aligned.m8n8.x4.shared.b16 {%0,%1,%2,%3}, [%4];" \
                 : "=r"(r0), "=r"(r1), "=r"(r2), "=r"(r3) : "r"(addr))

#define MMA16816(d, a0, a1, a2, a3, b0, b1) \
    asm volatile("mma.sync.aligned.m16n8k16.row.col.f32.bf16.bf16.f32 " \
                 "{%0,%1,%2,%3}, {%4,%5,%6,%7}, {%8,%9}, {%0,%1,%2,%3};" \
                 : "+f"((d)[0]), "+f"((d)[1]), "+f"((d)[2]), "+f"((d)[3]) \
                 : "r"(a0), "r"(a1), "r"(a2), "r"(a3), "r"(b0), "r"(b1))

__device__ __forceinline__ void bf16_split(float v, __nv_bfloat16& hi, __nv_bfloat16& lo) {
    hi = __float2bfloat16(v);
    lo = __float2bfloat16(v - __bfloat162float(hi));
}

__device__ __forceinline__ float softplus100(float v) {
    float y = 100.f * v;
    if (y > 20.f) return v;
    return log1pf(__expf(y)) * 0.01f;
}

// ---------------- weight-norm fold + bf16 hi/lo split ---------------------------
__global__ void prep_weights_tc(const float* __restrict__ v, const float* __restrict__ g,
                                int Kdim, int KPAD,
                                __nv_bfloat16* __restrict__ Whi,
                                __nv_bfloat16* __restrict__ Wlo,
                                float* __restrict__ lastrow)
{
    int j = blockIdx.x;
    const float* vr = v + (size_t)j * Kdim;
    __shared__ float red[256];
    float s = 0.f;
    for (int k = threadIdx.x; k < Kdim; k += 256) { float t = vr[k]; s += t * t; }
    red[threadIdx.x] = s;
    __syncthreads();
    for (int st = 128; st > 0; st >>= 1) {
        if (threadIdx.x < st) red[threadIdx.x] += red[threadIdx.x + st];
        __syncthreads();
    }
    float scale = g[j] * rsqrtf(red[0]);
    if (lastrow != nullptr && j == 256) {
        for (int k = threadIdx.x; k < Kdim; k += 256) lastrow[k] = vr[k] * scale;
        return;
    }
    for (int k = threadIdx.x; k < Kdim; k += 256) {
        float w = vr[k] * scale;
        __nv_bfloat16 hi, lo;
        bf16_split(w, hi, lo);
        Whi[(size_t)j * KPAD + k] = hi;
        Wlo[(size_t)j * KPAD + k] = lo;
    }
}

// ---------------- encode: pos-embed + multires hash grid (bf16 hi/lo out) -------
__global__ void encode_kernel(const float* __restrict__ x,
                              const float* __restrict__ tab,
                              __nv_bfloat16* __restrict__ Fhi,
                              __nv_bfloat16* __restrict__ Flo,
                              LevelParams lp)
{
    int i = blockIdx.x * blockDim.x + threadIdx.x;
    if (i >= NPTS) return;
    float px = x[3 * i + 0], py = x[3 * i + 1], pz = x[3 * i + 2];
    __nv_bfloat16* Fh = Fhi + (size_t)i * 128;
    __nv_bfloat16* Fl = Flo + (size_t)i * 128;

    auto put = [&](int c, float v) {
        __nv_bfloat16 hi, lo;
        bf16_split(v, hi, lo);
        Fh[c] = hi; Fl[c] = lo;
    };

    put(0, px); put(1, py); put(2, pz);
#pragma unroll
    for (int j = 0; j < 6; j++) {
        float f = (float)(1 << j);
        float s0, c0, s1, c1, s2, c2;
        sincosf(f * px, &s0, &c0);
        sincosf(f * py, &s1, &c1);
        sincosf(f * pz, &s2, &c2);
        put(3 + 6 * j + 0, s0); put(3 + 6 * j + 1, s1); put(3 + 6 * j + 2, s2);
        put(3 + 6 * j + 3, c0); put(3 + 6 * j + 4, c1); put(3 + 6 * j + 5, c2);
    }

    float xc = fminf(fmaxf(px, 0.f), 1.f);
    float yc = fminf(fmaxf(py, 0.f), 1.f);
    float zc = fminf(fmaxf(pz, 0.f), 1.f);

    for (int l = 0; l < 16; l++) {
        int   R  = lp.R[l];
        float Rf = (float)R;
        float fx = xc * Rf, fy = yc * Rf, fz = zc * Rf;
        float f0x = floorf(fx), f0y = floorf(fy), f0z = floorf(fz);
        float w1x = fx - f0x, w1y = fy - f0y, w1z = fz - f0z;
        float wx[2] = {1.f - w1x, w1x};
        float wy[2] = {1.f - w1y, w1y};
        float wz[2] = {1.f - w1z, w1z};
        unsigned ux = (unsigned)f0x, uy = (unsigned)f0y, uz = (unsigned)f0z;
        unsigned Ru = (unsigned)R, R1 = Ru + 1u;
        int dns = lp.dense[l];
        const float2* tabL = (const float2*)tab + (size_t)l * TSZ;
        float ax = 0.f, ay = 0.f;
#pragma unroll
        for (int c = 0; c < 8; c++) {
            unsigned ox = c & 1, oy = (c >> 1) & 1, oz = (c >> 2) & 1;
            unsigned ix = min(ux + ox, Ru);
            unsigned iy = min(uy + oy, Ru);
            unsigned iz = min(uz + oz, Ru);
            unsigned flat;
            if (dns) flat = ix + R1 * (iy + R1 * iz);
            else     flat = (ix ^ (iy * P1) ^ (iz * P2)) & (TSZ - 1u);
            float wc = wx[ox] * wy[oy] * wz[oz];
            float2 tv = __ldg(&tabL[flat]);
            ax = fmaf(wc, tv.x, ax);
            ay = fmaf(wc, tv.y, ay);
        }
        put(39 + 2 * l, ax);
        put(39 + 2 * l + 1, ay);
    }
}

// ---------------- bf16 split GEMM via mma.sync (HMMA) ---------------------------
// C[128 x 128 per CTA] = act(A @ W^T + bias); A [M][KPAD], W [256][KPAD], K-major
// bf16 hi/lo. acc += AhBh + AhBl + AlBh (fp32 accumulate).
// SMEM tiles: KC=32 (64B data/row), row stride 80B => conflict-free ldmatrix.
#define KC   32
#define RS   80                       // smem row stride bytes (5 x 16B)
#define ATB  (128 * RS)               // 10240 bytes per tile array
#define STG  (4 * ATB)                // Ah, Al, Bh, Bl per stage
#define SMEM_SZ (2 * STG)             // 81920

template<int KPAD, bool ACT, bool LAST>
__global__ __launch_bounds__(256, 2)
void gemm_mma(const __nv_bfloat16* __restrict__ Ah, const __nv_bfloat16* __restrict__ Al,
              const __nv_bfloat16* __restrict__ Bh, const __nv_bfloat16* __restrict__ Bl,
              const float* __restrict__ bias,
              __nv_bfloat16* __restrict__ Ohi, __nv_bfloat16* __restrict__ Olo,
              float* __restrict__ Of)
{
    constexpr int NC = KPAD / KC;
    extern __shared__ char smem[];
    uint32 sb = smem_u32(smem);

    const int tid  = threadIdx.x;
    const int lane = tid & 31;
    const int wid  = tid >> 5;
    const int warpM = wid & 3;        // 0..3 -> 32-row slice
    const int warpN = wid >> 2;       // 0..1 -> 64-col slice
    const int mBase = blockIdx.y * 128;
    const int nBase = blockIdx.x * 128;

    // global load mapping: per array 512 x 16B transfers; thread does idx, idx+256
    const int ldRow0 = tid >> 2, ldSlot = tid & 3;   // idx = tid
    const int ldRow1 = ldRow0 + 64;                  // idx = tid + 256

    const char* pAh = (const char*)(Ah + (size_t)mBase * KPAD);
    const char* pAl = (const char*)(Al + (size_t)mBase * KPAD);
    const char* pBh = (const char*)(Bh + (size_t)nBase * KPAD);
    const char* pBl = (const char*)(Bl + (size_t)nBase * KPAD);

    auto issue_chunk = [&](int c) {
        uint32 stage = sb + (c & 1) * STG;
        size_t gofs0 = (size_t)ldRow0 * (KPAD * 2) + c * (KC * 2) + ldSlot * 16;
        size_t gofs1 = (size_t)ldRow1 * (KPAD * 2) + c * (KC * 2) + ldSlot * 16;
        uint32 sofs0 = ldRow0 * RS + ldSlot * 16;
        uint32 sofs1 = ldRow1 * RS + ldSlot * 16;
        CP_ASYNC16(stage + 0 * ATB + sofs0, pAh + gofs0);
        CP_ASYNC16(stage + 0 * ATB + sofs1, pAh + gofs1);
        CP_ASYNC16(stage + 1 * ATB + sofs0, pAl + gofs0);
        CP_ASYNC16(stage + 1 * ATB + sofs1, pAl + gofs1);
        CP_ASYNC16(stage + 2 * ATB + sofs0, pBh + gofs0);
        CP_ASYNC16(stage + 2 * ATB + sofs1, pBh + gofs1);
        CP_ASYNC16(stage + 3 * ATB + sofs0, pBl + gofs0);
        CP_ASYNC16(stage + 3 * ATB + sofs1, pBl + gofs1);
        CP_COMMIT();
    };

    float acc[2][8][4];
#pragma unroll
    for (int mt = 0; mt < 2; mt++)
#pragma unroll
        for (int nt = 0; nt < 8; nt++)
#pragma unroll
            for (int q = 0; q < 4; q++) acc[mt][nt][q] = 0.f;

    // per-lane ldmatrix offsets (within tile array)
    const uint32 aOff = (uint32)(warpM * 32 + (lane & 15)) * RS + (lane >> 4) * 16;
    const uint32 bOff = (uint32)(warpN * 64 + (lane & 7) + ((lane >> 4) << 3)) * RS
                        + ((lane >> 3) & 1) * 16;

    issue_chunk(0);

    for (int c = 0; c < NC; c++) {
        if (c + 1 < NC) issue_chunk(c + 1);
        if (c + 1 < NC) { CP_WAIT(1); } else { CP_WAIT(0); }
        __syncthreads();

        uint32 stage = sb + (c & 1) * STG;
        uint32 sAh = stage + 0 * ATB + aOff;
        uint32 sAl = stage + 1 * ATB + aOff;
        uint32 sBh = stage + 2 * ATB + bOff;
        uint32 sBl = stage + 3 * ATB + bOff;

#pragma unroll
        for (int ks = 0; ks < 2; ks++) {
            uint32 kb = ks * (KC / 2) * 2;      // 32 bytes per k16 step
            uint32 ah[2][4], al[2][4];
            LDSM4(ah[0][0], ah[0][1], ah[0][2], ah[0][3], sAh + kb);
            LDSM4(ah[1][0], ah[1][1], ah[1][2], ah[1][3], sAh + 16 * RS + kb);
            LDSM4(al[0][0], al[0][1], al[0][2], al[0][3], sAl + kb);
            LDSM4(al[1][0], al[1][1], al[1][2], al[1][3], sAl + 16 * RS + kb);
#pragma unroll
            for (int np = 0; np < 4; np++) {
                uint32 bh[4], bl[4];
                LDSM4(bh[0], bh[1], bh[2], bh[3], sBh + np * 16 * RS + kb);
                LDSM4(bl[0], bl[1], bl[2], bl[3], sBl + np * 16 * RS + kb);
#pragma unroll
                for (int mt = 0; mt < 2; mt++) {
                    MMA16816(acc[mt][2 * np + 0], ah[mt][0], ah[mt][1], ah[mt][2], ah[mt][3], bh[0], bh[1]);
                    MMA16816(acc[mt][2 * np + 1], ah[mt][0], ah[mt][1], ah[mt][2], ah[mt][3], bh[2], bh[3]);
                    MMA16816(acc[mt][2 * np + 0], ah[mt][0], ah[mt][1], ah[mt][2], ah[mt][3], bl[0], bl[1]);
                    MMA16816(acc[mt][2 * np + 1], ah[mt][0], ah[mt][1], ah[mt][2], ah[mt][3], bl[2], bl[3]);
                    MMA16816(acc[mt][2 * np + 0], al[mt][0], al[mt][1], al[mt][2], al[mt][3], bh[0], bh[1]);
                    MMA16816(acc[mt][2 * np + 1], al[mt][0], al[mt][1], al[mt][2], al[mt][3], bh[2], bh[3]);
                }
            }
        }
        __syncthreads();
    }

    // ---------------- epilogue: bias + act + split + store ----------------------
#pragma unroll
    for (int mt = 0; mt < 2; mt++) {
        int m0 = mBase + warpM * 32 + mt * 16 + (lane >> 2);
#pragma unroll
        for (int nt = 0; nt < 8; nt++) {
            int n0 = nBase + warpN * 64 + nt * 8 + (lane & 3) * 2;
            float bj0 = __ldg(bias + n0), bj1 = __ldg(bias + n0 + 1);
#pragma unroll
            for (int half = 0; half < 2; half++) {
                int m = m0 + half * 8;
                float v0 = acc[mt][nt][2 * half + 0] + bj0;
                float v1 = acc[mt][nt][2 * half + 1] + bj1;
                if (ACT) { v0 = softplus100(v0); v1 = softplus100(v1); }
                if (LAST) {
                    float* orow = Of + (size_t)m * 257 + n0;
                    orow[0] = v0; orow[1] = v1;
                } else {
                    __nv_bfloat16 h0, l0, h1, l1;
                    bf16_split(v0, h0, l0);
                    bf16_split(v1, h1, l1);
                    __nv_bfloat162 hv; hv.x = h0; hv.y = h1;
                    __nv_bfloat162 lv; lv.x = l0; lv.y = l1;
                    *(__nv_bfloat162*)(Ohi + (size_t)m * 256 + n0) = hv;
                    *(__nv_bfloat162*)(Olo + (size_t)m * 256 + n0) = lv;
                }
            }
        }
    }
}

// ---------------- last output column (row 256 of v2) ----------------------------
__global__ void lastcol_kernel(const __nv_bfloat16* __restrict__ Hhi,
                               const __nv_bfloat16* __restrict__ Hlo,
                               const float* __restrict__ wlast,
                               const float* __restrict__ b2,
                               float* __restrict__ out)
{
    __shared__ float w[256];
    int tid = threadIdx.x;
    w[tid] = wlast[tid];
    __syncthreads();
    int lane = tid & 31, warp = tid >> 5;
    size_t i = (size_t)blockIdx.x * 8 + warp;
    const __nv_bfloat16* hh = Hhi + i * 256;
    const __nv_bfloat16* hl = Hlo + i * 256;
    float s = 0.f;
#pragma unroll
    for (int q = 0; q < 8; q++) {
        int k = lane + 32 * q;
        float h = __bfloat162float(hh[k]) + __bfloat162float(hl[k]);
        s = fmaf(h, w[k], s);
    }
#pragma unroll
    for (int off = 16; off > 0; off >>= 1) s += __shfl_xor_sync(0xffffffffu, s, off);
    if (lane == 0) out[i * 257 + 256] = s + b2[256];
}

// ---------------- launch --------------------------------------------------------
extern "C" void kernel_launch(void* const* d_in, const int* in_sizes, int n_in,
                              void* d_out, int out_size)
{
    const float* x      = (const float*)d_in[0];
    const float* tables = (const float*)d_in[1];
    const float* v0 = (const float*)d_in[2];
    const float* g0 = (const float*)d_in[3];
    const float* b0 = (const float*)d_in[4];
    const float* v1 = (const float*)d_in[5];
    const float* g1 = (const float*)d_in[6];
    const float* b1 = (const float*)d_in[7];
    const float* v2 = (const float*)d_in[8];
    const float* g2 = (const float*)d_in[9];
    const float* b2 = (const float*)d_in[10];
    float* out = (float*)d_out;

    __nv_bfloat16 *Fhi, *Flo, *H0hi, *H0lo, *H1hi, *H1lo;
    __nv_bfloat16 *W0hi, *W0lo, *W1hi, *W1lo, *W2hi, *W2lo;
    float* w2last;
    cudaGetSymbolAddress((void**)&Fhi,  g_Fhi);
    cudaGetSymbolAddress((void**)&Flo,  g_Flo);
    cudaGetSymbolAddress((void**)&H0hi, g_H0hi);
    cudaGetSymbolAddress((void**)&H0lo, g_H0lo);
    cudaGetSymbolAddress((void**)&H1hi, g_H1hi);
    cudaGetSymbolAddress((void**)&H1lo, g_H1lo);
    cudaGetSymbolAddress((void**)&W0hi, g_W0hi);
    cudaGetSymbolAddress((void**)&W0lo, g_W0lo);
    cudaGetSymbolAddress((void**)&W1hi, g_W1hi);
    cudaGetSymbolAddress((void**)&W1lo, g_W1lo);
    cudaGetSymbolAddress((void**)&W2hi, g_W2hi);
    cudaGetSymbolAddress((void**)&W2lo, g_W2lo);
    cudaGetSymbolAddress((void**)&w2last, g_w2last);

    LevelParams lp;
    double SCALE = pow(2.0, log2(2048.0 / 16.0) / 15.0);
    for (int l = 0; l < 16; l++) {
        int R = (int)ceil(16.0 * pow(SCALE, (double)l));
        lp.R[l] = R;
        long long cc = (long long)R + 1;
        lp.dense[l] = (cc * cc * cc <= (long long)TSZ) ? 1 : 0;
    }

    cudaFuncSetAttribute(gemm_mma<128, true,  false>, cudaFuncAttributeMaxDynamicSharedMemorySize, SMEM_SZ);
    cudaFuncSetAttribute(gemm_mma<256, true,  false>, cudaFuncAttributeMaxDynamicSharedMemorySize, SMEM_SZ);
    cudaFuncSetAttribute(gemm_mma<256, false, true >, cudaFuncAttributeMaxDynamicSharedMemorySize, SMEM_SZ);

    prep_weights_tc<<<256, 256>>>(v0, g0, 71,  128, W0hi, W0lo, nullptr);
    prep_weights_tc<<<256, 256>>>(v1, g1, 256, 256, W1hi, W1lo, nullptr);
    prep_weights_tc<<<257, 256>>>(v2, g2, 256, 256, W2hi, W2lo, w2last);

    encode_kernel<<<NPTS / 256, 256>>>(x, tables, Fhi, Flo, lp);

    dim3 grid(2, NPTS / 128);
    gemm_mma<128, true,  false><<<grid, 256, SMEM_SZ>>>(Fhi,  Flo,  W0hi, W0lo, b0, H0hi, H0lo, nullptr);
    gemm_mma<256, true,  false><<<grid, 256, SMEM_SZ>>>(H0hi, H0lo, W1hi, W1lo, b1, H1hi, H1lo, nullptr);
    gemm_mma<256, false, true ><<<grid, 256, SMEM_SZ>>>(H1hi, H1lo, W2hi, W2lo, b2, nullptr, nullptr, out);

    lastcol_kernel<<<NPTS / 8, 256>>>(H1hi, H1lo, w2last, b2, out);
}

// round 4
// speedup vs baseline: 2.0728x; 1.0714x over previous
#include <cuda_runtime.h>
#include <cuda_bf16.h>
#include <math.h>
#include <stdint.h>

typedef unsigned int uint32;

#define NPTS 524288
#define TSZ  (1u << 19)
#define P1   2654435761u
#define P2   805459861u

// ---------------- scratch (device globals; allocation-free rule) ----------------
// Padding regions (cols 71..127 of F, rows k>=71 of W0) are BSS-zero and never
// written by any kernel, so they stay zero across graph replays.
__device__ __nv_bfloat16 g_Fhi [(size_t)NPTS * 128];
__device__ __nv_bfloat16 g_Flo [(size_t)NPTS * 128];
__device__ __nv_bfloat16 g_H0hi[(size_t)NPTS * 256];
__device__ __nv_bfloat16 g_H0lo[(size_t)NPTS * 256];
__device__ __nv_bfloat16 g_H1hi[(size_t)NPTS * 256];
__device__ __nv_bfloat16 g_H1lo[(size_t)NPTS * 256];
__device__ __nv_bfloat16 g_W0hi[256 * 128];            // [N=256][Kpad=128] K-major
__device__ __nv_bfloat16 g_W0lo[256 * 128];
__device__ __nv_bfloat16 g_W1hi[256 * 256];
__device__ __nv_bfloat16 g_W1lo[256 * 256];
__device__ __nv_bfloat16 g_W2hi[256 * 256];            // rows 0..255 of v2
__device__ __nv_bfloat16 g_W2lo[256 * 256];
__device__ float         g_w2last[256];                // row 256 of v2 (folded)

struct LevelParams { int R[16]; int dense[16]; };

// ---------------- PTX helpers ---------------------------------------------------
__device__ __forceinline__ uint32 smem_u32(const void* p) {
    uint32 a;
    asm("{ .reg .u64 t; cvta.to.shared.u64 t, %1; cvt.u32.u64 %0, t; }" : "=r"(a) : "l"(p));
    return a;
}

#define CP_ASYNC16(dst, src) asm volatile("cp.async.cg.shared.global [%0], [%1], 16;" :: "r"(dst), "l"(src))
#define CP_COMMIT()          asm volatile("cp.async.commit_group;" ::: "memory")
#define CP_WAIT(n)           asm volatile("cp.async.wait_group %0;" :: "n"(n) : "memory")

#define LDSM4(r0, r1, r2, r3, addr) \
    asm volatile("ldmatrix.sync.aligned.m8n8.x4.shared.b16 {%0,%1,%2,%3}, [%4];" \
                 : "=r"(r0), "=r"(r1), "=r"(r2), "=r"(r3) : "r"(addr))

#define MMA16816(d, a0, a1, a2, a3, b0, b1) \
    asm volatile("mma.sync.aligned.m16n8k16.row.col.f32.bf16.bf16.f32 " \
                 "{%0,%1,%2,%3}, {%4,%5,%6,%7}, {%8,%9}, {%0,%1,%2,%3};" \
                 : "+f"((d)[0]), "+f"((d)[1]), "+f"((d)[2]), "+f"((d)[3]) \
                 : "r"(a0), "r"(a1), "r"(a2), "r"(a3), "r"(b0), "r"(b1))

__device__ __forceinline__ void bf16_split(float v, __nv_bfloat16& hi, __nv_bfloat16& lo) {
    hi = __float2bfloat16(v);
    lo = __float2bfloat16(v - __bfloat162float(hi));
}

__device__ __forceinline__ float softplus100(float v) {
    float y = 100.f * v;
    if (y > 20.f) return v;
    return log1pf(__expf(y)) * 0.01f;
}

// ---------------- weight-norm fold + bf16 hi/lo split ---------------------------
__global__ void prep_weights_tc(const float* __restrict__ v, const float* __restrict__ g,
                                int Kdim, int KPAD,
                                __nv_bfloat16* __restrict__ Whi,
                                __nv_bfloat16* __restrict__ Wlo,
                                float* __restrict__ lastrow)
{
    int j = blockIdx.x;
    const float* vr = v + (size_t)j * Kdim;
    __shared__ float red[256];
    float s = 0.f;
    for (int k = threadIdx.x; k < Kdim; k += 256) { float t = vr[k]; s += t * t; }
    red[threadIdx.x] = s;
    __syncthreads();
    for (int st = 128; st > 0; st >>= 1) {
        if (threadIdx.x < st) red[threadIdx.x] += red[threadIdx.x + st];
        __syncthreads();
    }
    float scale = g[j] * rsqrtf(red[0]);
    if (lastrow != nullptr && j == 256) {
        for (int k = threadIdx.x; k < Kdim; k += 256) lastrow[k] = vr[k] * scale;
        return;
    }
    for (int k = threadIdx.x; k < Kdim; k += 256) {
        float w = vr[k] * scale;
        __nv_bfloat16 hi, lo;
        bf16_split(w, hi, lo);
        Whi[(size_t)j * KPAD + k] = hi;
        Wlo[(size_t)j * KPAD + k] = lo;
    }
}

// ---------------- encode: pos-embed + multires hash grid (bf16 hi/lo out) -------
// All 72 features built in registers, then stored as 9x16B uint4 per array.
__global__ void encode_kernel(const float* __restrict__ x,
                              const float* __restrict__ tab,
                              __nv_bfloat16* __restrict__ Fhi,
                              __nv_bfloat16* __restrict__ Flo,
                              LevelParams lp)
{
    int i = blockIdx.x * blockDim.x + threadIdx.x;
    if (i >= NPTS) return;
    float px = x[3 * i + 0], py = x[3 * i + 1], pz = x[3 * i + 2];

    float vals[72];
    vals[0] = px; vals[1] = py; vals[2] = pz;
#pragma unroll
    for (int j = 0; j < 6; j++) {
        float f = (float)(1 << j);
        float s0, c0, s1, c1, s2, c2;
        __sincosf(f * px, &s0, &c0);
        __sincosf(f * py, &s1, &c1);
        __sincosf(f * pz, &s2, &c2);
        vals[3 + 6 * j + 0] = s0; vals[3 + 6 * j + 1] = s1; vals[3 + 6 * j + 2] = s2;
        vals[3 + 6 * j + 3] = c0; vals[3 + 6 * j + 4] = c1; vals[3 + 6 * j + 5] = c2;
    }

    float xc = fminf(fmaxf(px, 0.f), 1.f);
    float yc = fminf(fmaxf(py, 0.f), 1.f);
    float zc = fminf(fmaxf(pz, 0.f), 1.f);

    for (int l = 0; l < 16; l++) {
        int   R  = lp.R[l];
        float Rf = (float)R;
        float fx = xc * Rf, fy = yc * Rf, fz = zc * Rf;
        float f0x = floorf(fx), f0y = floorf(fy), f0z = floorf(fz);
        float w1x = fx - f0x, w1y = fy - f0y, w1z = fz - f0z;
        float wx[2] = {1.f - w1x, w1x};
        float wy[2] = {1.f - w1y, w1y};
        float wz[2] = {1.f - w1z, w1z};
        unsigned ux = (unsigned)f0x, uy = (unsigned)f0y, uz = (unsigned)f0z;
        unsigned Ru = (unsigned)R, R1 = Ru + 1u;
        int dns = lp.dense[l];
        const float2* tabL = (const float2*)tab + (size_t)l * TSZ;
        float ax = 0.f, ay = 0.f;
#pragma unroll
        for (int c = 0; c < 8; c++) {
            unsigned ox = c & 1, oy = (c >> 1) & 1, oz = (c >> 2) & 1;
            unsigned ix = min(ux + ox, Ru);
            unsigned iy = min(uy + oy, Ru);
            unsigned iz = min(uz + oz, Ru);
            unsigned flat;
            if (dns) flat = ix + R1 * (iy + R1 * iz);
            else     flat = (ix ^ (iy * P1) ^ (iz * P2)) & (TSZ - 1u);
            float wc = wx[ox] * wy[oy] * wz[oz];
            float2 tv = __ldg(&tabL[flat]);
            ax = fmaf(wc, tv.x, ax);
            ay = fmaf(wc, tv.y, ay);
        }
        vals[39 + 2 * l]     = ax;
        vals[40 + 2 * l]     = ay;
    }

    // vectorized hi/lo store: 9 x uint4 per array (cols 0..71)
    __nv_bfloat16* Fh = Fhi + (size_t)i * 128;
    __nv_bfloat16* Fl = Flo + (size_t)i * 128;
#pragma unroll
    for (int c0 = 0; c0 < 72; c0 += 8) {
        uint32 hw[4], lw[4];
#pragma unroll
        for (int q = 0; q < 4; q++) {
            float a = vals[c0 + 2 * q], b = vals[c0 + 2 * q + 1];
            __nv_bfloat16 ha, la, hb, lb;
            bf16_split(a, ha, la);
            bf16_split(b, hb, lb);
            __nv_bfloat162 hv; hv.x = ha; hv.y = hb;
            __nv_bfloat162 lv; lv.x = la; lv.y = lb;
            hw[q] = *(uint32*)&hv;
            lw[q] = *(uint32*)&lv;
        }
        *(uint4*)(Fh + c0) = make_uint4(hw[0], hw[1], hw[2], hw[3]);
        *(uint4*)(Fl + c0) = make_uint4(lw[0], lw[1], lw[2], lw[3]);
    }
}

// ---------------- bf16 split GEMM via mma.sync (HMMA) ---------------------------
// CTA tile 256(M) x 128(N), 512 threads (16 warps of 32x64), 3-stage cp.async
// pipeline, one __syncthreads per K-chunk. acc += AhBh + AhBl + AlBh.
#define KC   32
#define RS   80                        // smem row stride bytes (5 x 16B banks perm)
#define ATA  (256 * RS)                // A tile array bytes  (20480)
#define ATB  (128 * RS)                // B tile array bytes  (10240)
#define STG  (2 * ATA + 2 * ATB)       // Ah, Al, Bh, Bl      (61440)
#define NSTAGE 3
#define SMEM_SZ (NSTAGE * STG)         // 184320

template<int KPAD, bool ACT, bool LAST>
__global__ __launch_bounds__(512, 1)
void gemm_mma(const __nv_bfloat16* __restrict__ Ah, const __nv_bfloat16* __restrict__ Al,
              const __nv_bfloat16* __restrict__ Bh, const __nv_bfloat16* __restrict__ Bl,
              const float* __restrict__ bias,
              __nv_bfloat16* __restrict__ Ohi, __nv_bfloat16* __restrict__ Olo,
              float* __restrict__ Of)
{
    constexpr int NC = KPAD / KC;
    extern __shared__ char smem[];
    uint32 sb = smem_u32(smem);

    const int tid  = threadIdx.x;
    const int lane = tid & 31;
    const int wid  = tid >> 5;
    const int warpM = wid & 7;         // 0..7 -> 32-row slice
    const int warpN = wid >> 3;        // 0..1 -> 64-col slice
    const int mBase = blockIdx.y * 256;
    const int nBase = blockIdx.x * 128;

    // global load mapping (16B chunks): A arrays: 1024 chunks -> tid, tid+512
    //                                   B arrays: 512 chunks  -> tid
    const int aRow0 = tid >> 2,          aSlot = tid & 3;
    const int aRow1 = aRow0 + 128;
    const int bRow  = tid >> 2;

    const char* pAh = (const char*)(Ah + (size_t)mBase * KPAD);
    const char* pAl = (const char*)(Al + (size_t)mBase * KPAD);
    const char* pBh = (const char*)(Bh + (size_t)nBase * KPAD);
    const char* pBl = (const char*)(Bl + (size_t)nBase * KPAD);

    auto issue_chunk = [&](int c) {
        uint32 stage = sb + (c % NSTAGE) * STG;
        size_t ga0 = (size_t)aRow0 * (KPAD * 2) + c * (KC * 2) + aSlot * 16;
        size_t ga1 = (size_t)aRow1 * (KPAD * 2) + c * (KC * 2) + aSlot * 16;
        size_t gb  = (size_t)bRow  * (KPAD * 2) + c * (KC * 2) + aSlot * 16;
        uint32 sa0 = aRow0 * RS + aSlot * 16;
        uint32 sa1 = aRow1 * RS + aSlot * 16;
        uint32 sbo = bRow  * RS + aSlot * 16;
        CP_ASYNC16(stage + sa0,                 pAh + ga0);
        CP_ASYNC16(stage + sa1,                 pAh + ga1);
        CP_ASYNC16(stage + ATA + sa0,           pAl + ga0);
        CP_ASYNC16(stage + ATA + sa1,           pAl + ga1);
        CP_ASYNC16(stage + 2 * ATA + sbo,       pBh + gb);
        CP_ASYNC16(stage + 2 * ATA + ATB + sbo, pBl + gb);
        CP_COMMIT();
    };

    float acc[2][8][4];
#pragma unroll
    for (int mt = 0; mt < 2; mt++)
#pragma unroll
        for (int nt = 0; nt < 8; nt++)
#pragma unroll
            for (int q = 0; q < 4; q++) acc[mt][nt][q] = 0.f;

    const uint32 aOff = (uint32)(warpM * 32 + (lane & 15)) * RS + (lane >> 4) * 16;
    const uint32 bOff = (uint32)(warpN * 64 + (lane & 7) + ((lane >> 4) << 3)) * RS
                        + ((lane >> 3) & 1) * 16;

    issue_chunk(0);
    if (NC > 1) issue_chunk(1);

    for (int c = 0; c < NC; c++) {
        if (c + 1 < NC) { CP_WAIT(1); } else { CP_WAIT(0); }
        __syncthreads();
        if (c + 2 < NC) issue_chunk(c + 2);

        uint32 stage = sb + (c % NSTAGE) * STG;
        uint32 sAh = stage + aOff;
        uint32 sAl = stage + ATA + aOff;
        uint32 sBh = stage + 2 * ATA + bOff;
        uint32 sBl = stage + 2 * ATA + ATB + bOff;

#pragma unroll
        for (int ks = 0; ks < 2; ks++) {
            uint32 kb = ks * 32;               // 16 k-elems = 32 bytes
            uint32 ah[2][4], al[2][4];
            LDSM4(ah[0][0], ah[0][1], ah[0][2], ah[0][3], sAh + kb);
            LDSM4(ah[1][0], ah[1][1], ah[1][2], ah[1][3], sAh + 16 * RS + kb);
            LDSM4(al[0][0], al[0][1], al[0][2], al[0][3], sAl + kb);
            LDSM4(al[1][0], al[1][1], al[1][2], al[1][3], sAl + 16 * RS + kb);
#pragma unroll
            for (int np = 0; np < 4; np++) {
                uint32 bh[4], bl[4];
                LDSM4(bh[0], bh[1], bh[2], bh[3], sBh + np * 16 * RS + kb);
                LDSM4(bl[0], bl[1], bl[2], bl[3], sBl + np * 16 * RS + kb);
#pragma unroll
                for (int mt = 0; mt < 2; mt++) {
                    MMA16816(acc[mt][2 * np + 0], ah[mt][0], ah[mt][1], ah[mt][2], ah[mt][3], bh[0], bh[1]);
                    MMA16816(acc[mt][2 * np + 1], ah[mt][0], ah[mt][1], ah[mt][2], ah[mt][3], bh[2], bh[3]);
                    MMA16816(acc[mt][2 * np + 0], ah[mt][0], ah[mt][1], ah[mt][2], ah[mt][3], bl[0], bl[1]);
                    MMA16816(acc[mt][2 * np + 1], ah[mt][0], ah[mt][1], ah[mt][2], ah[mt][3], bl[2], bl[3]);
                    MMA16816(acc[mt][2 * np + 0], al[mt][0], al[mt][1], al[mt][2], al[mt][3], bh[0], bh[1]);
                    MMA16816(acc[mt][2 * np + 1], al[mt][0], al[mt][1], al[mt][2], al[mt][3], bh[2], bh[3]);
                }
            }
        }
        __syncthreads();
    }

    // ---------------- epilogue: bias + act + split + store ----------------------
#pragma unroll
    for (int mt = 0; mt < 2; mt++) {
        int m0 = mBase + warpM * 32 + mt * 16 + (lane >> 2);
#pragma unroll
        for (int nt = 0; nt < 8; nt++) {
            int n0 = nBase + warpN * 64 + nt * 8 + (lane & 3) * 2;
            float bj0 = __ldg(bias + n0), bj1 = __ldg(bias + n0 + 1);
#pragma unroll
            for (int half = 0; half < 2; half++) {
                int m = m0 + half * 8;
                float v0 = acc[mt][nt][2 * half + 0] + bj0;
                float v1 = acc[mt][nt][2 * half + 1] + bj1;
                if (ACT) { v0 = softplus100(v0); v1 = softplus100(v1); }
                if (LAST) {
                    float* orow = Of + (size_t)m * 257 + n0;
                    orow[0] = v0; orow[1] = v1;
                } else {
                    __nv_bfloat16 h0, l0, h1, l1;
                    bf16_split(v0, h0, l0);
                    bf16_split(v1, h1, l1);
                    __nv_bfloat162 hv; hv.x = h0; hv.y = h1;
                    __nv_bfloat162 lv; lv.x = l0; lv.y = l1;
                    *(__nv_bfloat162*)(Ohi + (size_t)m * 256 + n0) = hv;
                    *(__nv_bfloat162*)(Olo + (size_t)m * 256 + n0) = lv;
                }
            }
        }
    }
}

// ---------------- last output column (row 256 of v2) ----------------------------
__global__ void lastcol_kernel(const __nv_bfloat16* __restrict__ Hhi,
                               const __nv_bfloat16* __restrict__ Hlo,
                               const float* __restrict__ wlast,
                               const float* __restrict__ b2,
                               float* __restrict__ out)
{
    __shared__ float w[256];
    int tid = threadIdx.x;
    w[tid] = wlast[tid];
    __syncthreads();
    int lane = tid & 31, warp = tid >> 5;
    size_t i = (size_t)blockIdx.x * 8 + warp;
    const __nv_bfloat16* hh = Hhi + i * 256;
    const __nv_bfloat16* hl = Hlo + i * 256;
    float s = 0.f;
#pragma unroll
    for (int q = 0; q < 8; q++) {
        int k = lane + 32 * q;
        float h = __bfloat162float(hh[k]) + __bfloat162float(hl[k]);
        s = fmaf(h, w[k], s);
    }
#pragma unroll
    for (int off = 16; off > 0; off >>= 1) s += __shfl_xor_sync(0xffffffffu, s, off);
    if (lane == 0) out[i * 257 + 256] = s + b2[256];
}

// ---------------- launch --------------------------------------------------------
extern "C" void kernel_launch(void* const* d_in, const int* in_sizes, int n_in,
                              void* d_out, int out_size)
{
    const float* x      = (const float*)d_in[0];
    const float* tables = (const float*)d_in[1];
    const float* v0 = (const float*)d_in[2];
    const float* g0 = (const float*)d_in[3];
    const float* b0 = (const float*)d_in[4];
    const float* v1 = (const float*)d_in[5];
    const float* g1 = (const float*)d_in[6];
    const float* b1 = (const float*)d_in[7];
    const float* v2 = (const float*)d_in[8];
    const float* g2 = (const float*)d_in[9];
    const float* b2 = (const float*)d_in[10];
    float* out = (float*)d_out;

    __nv_bfloat16 *Fhi, *Flo, *H0hi, *H0lo, *H1hi, *H1lo;
    __nv_bfloat16 *W0hi, *W0lo, *W1hi, *W1lo, *W2hi, *W2lo;
    float* w2last;
    cudaGetSymbolAddress((void**)&Fhi,  g_Fhi);
    cudaGetSymbolAddress((void**)&Flo,  g_Flo);
    cudaGetSymbolAddress((void**)&H0hi, g_H0hi);
    cudaGetSymbolAddress((void**)&H0lo, g_H0lo);
    cudaGetSymbolAddress((void**)&H1hi, g_H1hi);
    cudaGetSymbolAddress((void**)&H1lo, g_H1lo);
    cudaGetSymbolAddress((void**)&W0hi, g_W0hi);
    cudaGetSymbolAddress((void**)&W0lo, g_W0lo);
    cudaGetSymbolAddress((void**)&W1hi, g_W1hi);
    cudaGetSymbolAddress((void**)&W1lo, g_W1lo);
    cudaGetSymbolAddress((void**)&W2hi, g_W2hi);
    cudaGetSymbolAddress((void**)&W2lo, g_W2lo);
    cudaGetSymbolAddress((void**)&w2last, g_w2last);

    LevelParams lp;
    double SCALE = pow(2.0, log2(2048.0 / 16.0) / 15.0);
    for (int l = 0; l < 16; l++) {
        int R = (int)ceil(16.0 * pow(SCALE, (double)l));
        lp.R[l] = R;
        long long cc = (long long)R + 1;
        lp.dense[l] = (cc * cc * cc <= (long long)TSZ) ? 1 : 0;
    }

    cudaFuncSetAttribute(gemm_mma<128, true,  false>, cudaFuncAttributeMaxDynamicSharedMemorySize, SMEM_SZ);
    cudaFuncSetAttribute(gemm_mma<256, true,  false>, cudaFuncAttributeMaxDynamicSharedMemorySize, SMEM_SZ);
    cudaFuncSetAttribute(gemm_mma<256, false, true >, cudaFuncAttributeMaxDynamicSharedMemorySize, SMEM_SZ);

    prep_weights_tc<<<256, 256>>>(v0, g0, 71,  128, W0hi, W0lo, nullptr);
    prep_weights_tc<<<256, 256>>>(v1, g1, 256, 256, W1hi, W1lo, nullptr);
    prep_weights_tc<<<257, 256>>>(v2, g2, 256, 256, W2hi, W2lo, w2last);

    encode_kernel<<<NPTS / 256, 256>>>(x, tables, Fhi, Flo, lp);

    dim3 grid(2, NPTS / 256);
    gemm_mma<128, true,  false><<<grid, 512, SMEM_SZ>>>(Fhi,  Flo,  W0hi, W0lo, b0, H0hi, H0lo, nullptr);
    gemm_mma<256, true,  false><<<grid, 512, SMEM_SZ>>>(H0hi, H0lo, W1hi, W1lo, b1, H1hi, H1lo, nullptr);
    gemm_mma<256, false, true ><<<grid, 512, SMEM_SZ>>>(H1hi, H1lo, W2hi, W2lo, b2, nullptr, nullptr, out);

    lastcol_kernel<<<NPTS / 8, 256>>>(H1hi, H1lo, w2last, b2, out);
}

// round 6
// speedup vs baseline: 2.4205x; 1.1677x over previous
#include <cuda_runtime.h>
#include <cuda_bf16.h>
#include <math.h>
#include <stdint.h>

typedef unsigned int uint32;

#define NPTS 524288
#define TSZ  (1u << 19)
#define P1   2654435761u
#define P2   805459861u

#define KP0  96                        // layer-0 K padding (71 real cols)

// ---------------- scratch (device globals; allocation-free rule) ----------------
// Padding regions (cols 71..95 of F, rows k>=71 of W0) are BSS-zero and never
// written by any kernel, so they stay zero across graph replays.
__device__ __nv_bfloat16 g_Fhi [(size_t)NPTS * KP0];
__device__ __nv_bfloat16 g_Flo [(size_t)NPTS * KP0];
__device__ __nv_bfloat16 g_H0hi[(size_t)NPTS * 256];
__device__ __nv_bfloat16 g_H0lo[(size_t)NPTS * 256];
__device__ __nv_bfloat16 g_H1hi[(size_t)NPTS * 256];
__device__ __nv_bfloat16 g_H1lo[(size_t)NPTS * 256];
__device__ __nv_bfloat16 g_W0hi[256 * KP0];            // [N=256][Kpad] K-major
__device__ __nv_bfloat16 g_W0lo[256 * KP0];
__device__ __nv_bfloat16 g_W1hi[256 * 256];
__device__ __nv_bfloat16 g_W1lo[256 * 256];
__device__ __nv_bfloat16 g_W2hi[256 * 256];            // rows 0..255 of v2
__device__ __nv_bfloat16 g_W2lo[256 * 256];
__device__ float         g_w2last[256];                // row 256 of v2 (folded)

struct LevelParams { int R[16]; int dense[16]; };

// ---------------- PTX helpers ---------------------------------------------------
__device__ __forceinline__ uint32 smem_u32(const void* p) {
    uint32 a;
    asm("{ .reg .u64 t; cvta.to.shared.u64 t, %1; cvt.u32.u64 %0, t; }" : "=r"(a) : "l"(p));
    return a;
}

#define CP_ASYNC16(dst, src) asm volatile("cp.async.cg.shared.global [%0], [%1], 16;" :: "r"(dst), "l"(src))
#define CP_COMMIT()          asm volatile("cp.async.commit_group;" ::: "memory")
#define CP_WAIT(n)           asm volatile("cp.async.wait_group %0;" :: "n"(n) : "memory")

#define LDSM4(r0, r1, r2, r3, addr) \
    asm volatile("ldmatrix.sync.aligned.m8n8.x4.shared.b16 {%0,%1,%2,%3}, [%4];" \
                 : "=r"(r0), "=r"(r1), "=r"(r2), "=r"(r3) : "r"(addr))

#define MMA16816(d, a0, a1, a2, a3, b0, b1) \
    asm volatile("mma.sync.aligned.m16n8k16.row.col.f32.bf16.bf16.f32 " \
                 "{%0,%1,%2,%3}, {%4,%5,%6,%7}, {%8,%9}, {%0,%1,%2,%3};" \
                 : "+f"((d)[0]), "+f"((d)[1]), "+f"((d)[2]), "+f"((d)[3]) \
                 : "r"(a0), "r"(a1), "r"(a2), "r"(a3), "r"(b0), "r"(b1))

__device__ __forceinline__ void bf16_split(float v, __nv_bfloat16& hi, __nv_bfloat16& lo) {
    hi = __float2bfloat16(v);
    lo = __float2bfloat16(v - __bfloat162float(hi));
}

__device__ __forceinline__ float softplus100(float v) {
    float y = 100.f * v;
    if (y > 20.f) return v;
    return log1pf(__expf(y)) * 0.01f;
}

// ---------------- weight-norm fold + bf16 hi/lo split ---------------------------
__global__ void prep_weights_tc(const float* __restrict__ v, const float* __restrict__ g,
                                int Kdim, int KPAD,
                                __nv_bfloat16* __restrict__ Whi,
                                __nv_bfloat16* __restrict__ Wlo,
                                float* __restrict__ lastrow)
{
    int j = blockIdx.x;
    const float* vr = v + (size_t)j * Kdim;
    __shared__ float red[256];
    float s = 0.f;
    for (int k = threadIdx.x; k < Kdim; k += 256) { float t = vr[k]; s += t * t; }
    red[threadIdx.x] = s;
    __syncthreads();
    for (int st = 128; st > 0; st >>= 1) {
        if (threadIdx.x < st) red[threadIdx.x] += red[threadIdx.x + st];
        __syncthreads();
    }
    float scale = g[j] * rsqrtf(red[0]);
    if (lastrow != nullptr && j == 256) {
        for (int k = threadIdx.x; k < Kdim; k += 256) lastrow[k] = vr[k] * scale;
        return;
    }
    for (int k = threadIdx.x; k < Kdim; k += 256) {
        float w = vr[k] * scale;
        __nv_bfloat16 hi, lo;
        bf16_split(w, hi, lo);
        Whi[(size_t)j * KPAD + k] = hi;
        Wlo[(size_t)j * KPAD + k] = lo;
    }
}

// ---------------- encode: pos-embed + multires hash grid (bf16 hi/lo out) -------
__global__ void encode_kernel(const float* __restrict__ x,
                              const float* __restrict__ tab,
                              __nv_bfloat16* __restrict__ Fhi,
                              __nv_bfloat16* __restrict__ Flo,
                              LevelParams lp)
{
    int i = blockIdx.x * blockDim.x + threadIdx.x;
    if (i >= NPTS) return;
    float px = x[3 * i + 0], py = x[3 * i + 1], pz = x[3 * i + 2];

    float vals[72];
    vals[0] = px; vals[1] = py; vals[2] = pz;
#pragma unroll
    for (int j = 0; j < 6; j++) {
        float f = (float)(1 << j);
        float s0, c0, s1, c1, s2, c2;
        __sincosf(f * px, &s0, &c0);
        __sincosf(f * py, &s1, &c1);
        __sincosf(f * pz, &s2, &c2);
        vals[3 + 6 * j + 0] = s0; vals[3 + 6 * j + 1] = s1; vals[3 + 6 * j + 2] = s2;
        vals[3 + 6 * j + 3] = c0; vals[3 + 6 * j + 4] = c1; vals[3 + 6 * j + 5] = c2;
    }

    float xc = fminf(fmaxf(px, 0.f), 1.f);
    float yc = fminf(fmaxf(py, 0.f), 1.f);
    float zc = fminf(fmaxf(pz, 0.f), 1.f);

    for (int l = 0; l < 16; l++) {
        int   R  = lp.R[l];
        float Rf = (float)R;
        float fx = xc * Rf, fy = yc * Rf, fz = zc * Rf;
        float f0x = floorf(fx), f0y = floorf(fy), f0z = floorf(fz);
        float w1x = fx - f0x, w1y = fy - f0y, w1z = fz - f0z;
        float wx[2] = {1.f - w1x, w1x};
        float wy[2] = {1.f - w1y, w1y};
        float wz[2] = {1.f - w1z, w1z};
        unsigned ux = (unsigned)f0x, uy = (unsigned)f0y, uz = (unsigned)f0z;
        unsigned Ru = (unsigned)R, R1 = Ru + 1u;
        int dns = lp.dense[l];
        const float2* tabL = (const float2*)tab + (size_t)l * TSZ;
        float ax = 0.f, ay = 0.f;
#pragma unroll
        for (int c = 0; c < 8; c++) {
            unsigned ox = c & 1, oy = (c >> 1) & 1, oz = (c >> 2) & 1;
            unsigned ix = min(ux + ox, Ru);
            unsigned iy = min(uy + oy, Ru);
            unsigned iz = min(uz + oz, Ru);
            unsigned flat;
            if (dns) flat = ix + R1 * (iy + R1 * iz);
            else     flat = (ix ^ (iy * P1) ^ (iz * P2)) & (TSZ - 1u);
            float wc = wx[ox] * wy[oy] * wz[oz];
            float2 tv = __ldg(&tabL[flat]);
            ax = fmaf(wc, tv.x, ax);
            ay = fmaf(wc, tv.y, ay);
        }
        vals[39 + 2 * l] = ax;
        vals[40 + 2 * l] = ay;
    }

    // vectorized hi/lo store: 9 x uint4 per array (cols 0..71)
    __nv_bfloat16* Fh = Fhi + (size_t)i * KP0;
    __nv_bfloat16* Fl = Flo + (size_t)i * KP0;
#pragma unroll
    for (int c0 = 0; c0 < 72; c0 += 8) {
        uint32 hw[4], lw[4];
#pragma unroll
        for (int q = 0; q < 4; q++) {
            float a = vals[c0 + 2 * q], b = vals[c0 + 2 * q + 1];
            __nv_bfloat16 ha, la, hb, lb;
            bf16_split(a, ha, la);
            bf16_split(b, hb, lb);
            __nv_bfloat162 hv; hv.x = ha; hv.y = hb;
            __nv_bfloat162 lv; lv.x = la; lv.y = lb;
            hw[q] = *(uint32*)&hv;
            lw[q] = *(uint32*)&lv;
        }
        *(uint4*)(Fh + c0) = make_uint4(hw[0], hw[1], hw[2], hw[3]);
        *(uint4*)(Fl + c0) = make_uint4(lw[0], lw[1], lw[2], lw[3]);
    }
}

// ---------------- bf16 split GEMM via mma.sync (HMMA) ---------------------------
// CTA tile 128(M) x 128(N), 256 threads (8 warps of 32x64), 2-stage cp.async,
// SINGLE __syncthreads per K-chunk. acc += AhBh + AhBl + AlBh.
#define KC   32
#define RS   80                        // smem row stride bytes (bank-permuting pad)
#define ATB  (128 * RS)                // 10240 bytes per tile array
#define STG  (4 * ATB)                 // Ah, Al, Bh, Bl per stage (40960)
#define SMEM_SZ (2 * STG)              // 81920 -> 2 CTAs/SM

template<int KPAD, bool ACT, bool LAST>
__global__ __launch_bounds__(256, 2)
void gemm_mma(const __nv_bfloat16* __restrict__ Ah, const __nv_bfloat16* __restrict__ Al,
              const __nv_bfloat16* __restrict__ Bh, const __nv_bfloat16* __restrict__ Bl,
              const float* __restrict__ bias,
              __nv_bfloat16* __restrict__ Ohi, __nv_bfloat16* __restrict__ Olo,
              float* __restrict__ Of)
{
    constexpr int NC = KPAD / KC;
    extern __shared__ char smem[];
    uint32 sb = smem_u32(smem);

    const int tid  = threadIdx.x;
    const int lane = tid & 31;
    const int wid  = tid >> 5;
    const int warpM = wid & 3;         // 0..3 -> 32-row slice
    const int warpN = wid >> 2;        // 0..1 -> 64-col slice
    const int mBase = blockIdx.y * 128;
    const int nBase = blockIdx.x * 128;

    // global load mapping: per array 512 x 16B transfers; thread does idx, idx+256
    const int ldRow0 = tid >> 2, ldSlot = tid & 3;
    const int ldRow1 = ldRow0 + 64;

    const char* pAh = (const char*)(Ah + (size_t)mBase * KPAD);
    const char* pAl = (const char*)(Al + (size_t)mBase * KPAD);
    const char* pBh = (const char*)(Bh + (size_t)nBase * KPAD);
    const char* pBl = (const char*)(Bl + (size_t)nBase * KPAD);

    auto issue_chunk = [&](int c) {
        uint32 stage = sb + (c & 1) * STG;
        size_t gofs0 = (size_t)ldRow0 * (KPAD * 2) + c * (KC * 2) + ldSlot * 16;
        size_t gofs1 = (size_t)ldRow1 * (KPAD * 2) + c * (KC * 2) + ldSlot * 16;
        uint32 sofs0 = ldRow0 * RS + ldSlot * 16;
        uint32 sofs1 = ldRow1 * RS + ldSlot * 16;
        CP_ASYNC16(stage + 0 * ATB + sofs0, pAh + gofs0);
        CP_ASYNC16(stage + 0 * ATB + sofs1, pAh + gofs1);
        CP_ASYNC16(stage + 1 * ATB + sofs0, pAl + gofs0);
        CP_ASYNC16(stage + 1 * ATB + sofs1, pAl + gofs1);
        CP_ASYNC16(stage + 2 * ATB + sofs0, pBh + gofs0);
        CP_ASYNC16(stage + 2 * ATB + sofs1, pBh + gofs1);
        CP_ASYNC16(stage + 3 * ATB + sofs0, pBl + gofs0);
        CP_ASYNC16(stage + 3 * ATB + sofs1, pBl + gofs1);
        CP_COMMIT();
    };

    float acc[2][8][4];
#pragma unroll
    for (int mt = 0; mt < 2; mt++)
#pragma unroll
        for (int nt = 0; nt < 8; nt++)
#pragma unroll
            for (int q = 0; q < 4; q++) acc[mt][nt][q] = 0.f;

    const uint32 aOff = (uint32)(warpM * 32 + (lane & 15)) * RS + (lane >> 4) * 16;
    const uint32 bOff = (uint32)(warpN * 64 + (lane & 7) + ((lane >> 4) << 3)) * RS
                        + ((lane >> 3) & 1) * 16;

    issue_chunk(0);

    for (int c = 0; c < NC; c++) {
        // sync ends compute of chunk c-1 (buffer (c+1)&1) -> safe to refill it
        __syncthreads();
        if (c + 1 < NC) { issue_chunk(c + 1); CP_WAIT(1); }
        else            { CP_WAIT(0); }
        // chunk c has landed; chunk c+1 may still be in flight

        uint32 stage = sb + (c & 1) * STG;
        uint32 sAh = stage + aOff;
        uint32 sAl = stage + ATB + aOff;
        uint32 sBh = stage + 2 * ATB + bOff;
        uint32 sBl = stage + 3 * ATB + bOff;

        // smem visibility of cp.async data needs a barrier after wait:
        __syncthreads();

#pragma unroll
        for (int ks = 0; ks < 2; ks++) {
            uint32 kb = ks * 32;               // 16 k-elems = 32 bytes
            uint32 ah[2][4], al[2][4];
            LDSM4(ah[0][0], ah[0][1], ah[0][2], ah[0][3], sAh + kb);
            LDSM4(ah[1][0], ah[1][1], ah[1][2], ah[1][3], sAh + 16 * RS + kb);
            LDSM4(al[0][0], al[0][1], al[0][2], al[0][3], sAl + kb);
            LDSM4(al[1][0], al[1][1], al[1][2], al[1][3], sAl + 16 * RS + kb);
#pragma unroll
            for (int np = 0; np < 4; np++) {
                uint32 bh[4], bl[4];
                LDSM4(bh[0], bh[1], bh[2], bh[3], sBh + np * 16 * RS + kb);
                LDSM4(bl[0], bl[1], bl[2], bl[3], sBl + np * 16 * RS + kb);
#pragma unroll
                for (int mt = 0; mt < 2; mt++) {
                    MMA16816(acc[mt][2 * np + 0], ah[mt][0], ah[mt][1], ah[mt][2], ah[mt][3], bh[0], bh[1]);
                    MMA16816(acc[mt][2 * np + 1], ah[mt][0], ah[mt][1], ah[mt][2], ah[mt][3], bh[2], bh[3]);
                    MMA16816(acc[mt][2 * np + 0], ah[mt][0], ah[mt][1], ah[mt][2], ah[mt][3], bl[0], bl[1]);
                    MMA16816(acc[mt][2 * np + 1], ah[mt][0], ah[mt][1], ah[mt][2], ah[mt][3], bl[2], bl[3]);
                    MMA16816(acc[mt][2 * np + 0], al[mt][0], al[mt][1], al[mt][2], al[mt][3], bh[0], bh[1]);
                    MMA16816(acc[mt][2 * np + 1], al[mt][0], al[mt][1], al[mt][2], al[mt][3], bh[2], bh[3]);
                }
            }
        }
    }

    // ---------------- epilogue: bias + act + split + store ----------------------
#pragma unroll
    for (int mt = 0; mt < 2; mt++) {
        int m0 = mBase + warpM * 32 + mt * 16 + (lane >> 2);
#pragma unroll
        for (int nt = 0; nt < 8; nt++) {
            int n0 = nBase + warpN * 64 + nt * 8 + (lane & 3) * 2;
            float bj0 = __ldg(bias + n0), bj1 = __ldg(bias + n0 + 1);
#pragma unroll
            for (int half = 0; half < 2; half++) {
                int m = m0 + half * 8;
                float v0 = acc[mt][nt][2 * half + 0] + bj0;
                float v1 = acc[mt][nt][2 * half + 1] + bj1;
                if (ACT) { v0 = softplus100(v0); v1 = softplus100(v1); }
                if (LAST) {
                    float* orow = Of + (size_t)m * 257 + n0;
                    orow[0] = v0; orow[1] = v1;
                } else {
                    __nv_bfloat16 h0, l0, h1, l1;
                    bf16_split(v0, h0, l0);
                    bf16_split(v1, h1, l1);
                    __nv_bfloat162 hv; hv.x = h0; hv.y = h1;
                    __nv_bfloat162 lv; lv.x = l0; lv.y = l1;
                    *(__nv_bfloat162*)(Ohi + (size_t)m * 256 + n0) = hv;
                    *(__nv_bfloat162*)(Olo + (size_t)m * 256 + n0) = lv;
                }
            }
        }
    }
}

// ---------------- last output column (row 256 of v2) ----------------------------
__global__ void lastcol_kernel(const __nv_bfloat16* __restrict__ Hhi,
                               const __nv_bfloat16* __restrict__ Hlo,
                               const float* __restrict__ wlast,
                               const float* __restrict__ b2,
                               float* __restrict__ out)
{
    __shared__ float w[256];
    int tid = threadIdx.x;
    w[tid] = wlast[tid];
    __syncthreads();
    int lane = tid & 31, warp = tid >> 5;
    size_t i = (size_t)blockIdx.x * 8 + warp;
    const __nv_bfloat16* hh = Hhi + i * 256;
    const __nv_bfloat16* hl = Hlo + i * 256;
    float s = 0.f;
#pragma unroll
    for (int q = 0; q < 8; q++) {
        int k = lane + 32 * q;
        float h = __bfloat162float(hh[k]) + __bfloat162float(hl[k]);
        s = fmaf(h, w[k], s);
    }
#pragma unroll
    for (int off = 16; off > 0; off >>= 1) s += __shfl_xor_sync(0xffffffffu, s, off);
    if (lane == 0) out[i * 257 + 256] = s + b2[256];
}

// ---------------- launch --------------------------------------------------------
extern "C" void kernel_launch(void* const* d_in, const int* in_sizes, int n_in,
                              void* d_out, int out_size)
{
    const float* x      = (const float*)d_in[0];
    const float* tables = (const float*)d_in[1];
    const float* v0 = (const float*)d_in[2];
    const float* g0 = (const float*)d_in[3];
    const float* b0 = (const float*)d_in[4];
    const float* v1 = (const float*)d_in[5];
    const float* g1 = (const float*)d_in[6];
    const float* b1 = (const float*)d_in[7];
    const float* v2 = (const float*)d_in[8];
    const float* g2 = (const float*)d_in[9];
    const float* b2 = (const float*)d_in[10];
    float* out = (float*)d_out;

    __nv_bfloat16 *Fhi, *Flo, *H0hi, *H0lo, *H1hi, *H1lo;
    __nv_bfloat16 *W0hi, *W0lo, *W1hi, *W1lo, *W2hi, *W2lo;
    float* w2last;
    cudaGetSymbolAddress((void**)&Fhi,  g_Fhi);
    cudaGetSymbolAddress((void**)&Flo,  g_Flo);
    cudaGetSymbolAddress((void**)&H0hi, g_H0hi);
    cudaGetSymbolAddress((void**)&H0lo, g_H0lo);
    cudaGetSymbolAddress((void**)&H1hi, g_H1hi);
    cudaGetSymbolAddress((void**)&H1lo, g_H1lo);
    cudaGetSymbolAddress((void**)&W0hi, g_W0hi);
    cudaGetSymbolAddress((void**)&W0lo, g_W0lo);
    cudaGetSymbolAddress((void**)&W1hi, g_W1hi);
    cudaGetSymbolAddress((void**)&W1lo, g_W1lo);
    cudaGetSymbolAddress((void**)&W2hi, g_W2hi);
    cudaGetSymbolAddress((void**)&W2lo, g_W2lo);
    cudaGetSymbolAddress((void**)&w2last, g_w2last);

    LevelParams lp;
    double SCALE = pow(2.0, log2(2048.0 / 16.0) / 15.0);
    for (int l = 0; l < 16; l++) {
        int R = (int)ceil(16.0 * pow(SCALE, (double)l));
        lp.R[l] = R;
        long long cc = (long long)R + 1;
        lp.dense[l] = (cc * cc * cc <= (long long)TSZ) ? 1 : 0;
    }

    cudaFuncSetAttribute(gemm_mma<KP0, true,  false>, cudaFuncAttributeMaxDynamicSharedMemorySize, SMEM_SZ);
    cudaFuncSetAttribute(gemm_mma<256, true,  false>, cudaFuncAttributeMaxDynamicSharedMemorySize, SMEM_SZ);
    cudaFuncSetAttribute(gemm_mma<256, false, true >, cudaFuncAttributeMaxDynamicSharedMemorySize, SMEM_SZ);

    prep_weights_tc<<<256, 256>>>(v0, g0, 71,  KP0, W0hi, W0lo, nullptr);
    prep_weights_tc<<<256, 256>>>(v1, g1, 256, 256, W1hi, W1lo, nullptr);
    prep_weights_tc<<<257, 256>>>(v2, g2, 256, 256, W2hi, W2lo, w2last);

    encode_kernel<<<NPTS / 256, 256>>>(x, tables, Fhi, Flo, lp);

    dim3 grid(2, NPTS / 128);
    gemm_mma<KP0, true,  false><<<grid, 256, SMEM_SZ>>>(Fhi,  Flo,  W0hi, W0lo, b0, H0hi, H0lo, nullptr);
    gemm_mma<256, true,  false><<<grid, 256, SMEM_SZ>>>(H0hi, H0lo, W1hi, W1lo, b1, H1hi, H1lo, nullptr);
    gemm_mma<256, false, true ><<<grid, 256, SMEM_SZ>>>(H1hi, H1lo, W2hi, W2lo, b2, nullptr, nullptr, out);

    lastcol_kernel<<<NPTS / 8, 256>>>(H1hi, H1lo, w2last, b2, out);
}